// round 4
// baseline (speedup 1.0000x reference)
#include <cuda_runtime.h>
#include <math.h>
#include <stdint.h>

#define NN   20000
#define EE   320000
#define FIN  256
#define H1   512
#define NHEAD 8
#define NCLS 64
#define NEG  0.2f
#define EPSI 1e-16f

// ---------------- scratch (static device globals; no allocation) ----------------
__device__ float g_p1[NN * 1024];        // fused layer-1 proj: xl=[0,512), xr=[512,1024)
__device__ float g_h [NN * H1];
__device__ float g_alpha1[EE * NHEAD];
__device__ float g_inv1[NN * NHEAD];
__device__ float g_p2[NN * 128];         // fused layer-2 proj: xl=[0,64), xr=[64,128)
__device__ float g_alpha2[EE];
__device__ float g_inv2[NN];
__device__ int   g_deg[NN];
__device__ int   g_off[NN];
__device__ int   g_cur[NN];
__device__ int   g_elist[EE];
// concatenated transposed weights (K-major rows)
__device__ float g_wtc1[1024 * FIN];     // rows 0-511 = Wl1^T, 512-1023 = Wr1^T
__device__ float g_wtc2[128 * H1];       // rows 0-63 = Wl2^T, 64-127 = Wr2^T

// ---------------- tf32 / cp.async helpers ----------------
__device__ __forceinline__ uint32_t f2tf32(float f) {
    uint32_t u;
    asm("cvt.rna.tf32.f32 %0, %1;" : "=r"(u) : "f"(f));
    return u;
}
__device__ __forceinline__ uint32_t smem_u32(const void* p) {
    uint32_t a;
    asm("{ .reg .u64 t; cvta.to.shared.u64 t, %1; cvt.u32.u64 %0, t; }" : "=r"(a) : "l"(p));
    return a;
}
__device__ __forceinline__ void cp16(uint32_t daddr, const void* g, int sz) {
    asm volatile("cp.async.cg.shared.global [%0], [%1], 16, %2;"
                 :: "r"(daddr), "l"(g), "r"(sz));
}
#define CP_COMMIT() asm volatile("cp.async.commit_group;")
template <int N>
__device__ __forceinline__ void cp_wait() {
    asm volatile("cp.async.wait_group %0;" :: "n"(N));
}

__device__ __forceinline__ void mma_tf32(float c[4], uint32_t a0, uint32_t a1,
                                         uint32_t a2, uint32_t a3,
                                         uint32_t b0, uint32_t b1) {
    asm volatile(
        "mma.sync.aligned.m16n8k8.row.col.f32.tf32.tf32.f32 "
        "{%0,%1,%2,%3}, {%4,%5,%6,%7}, {%8,%9}, {%0,%1,%2,%3};"
        : "+f"(c[0]), "+f"(c[1]), "+f"(c[2]), "+f"(c[3])
        : "r"(a0), "r"(a1), "r"(a2), "r"(a3), "r"(b0), "r"(b1));
}

// ---------------- 3xTF32 GEMM: C[M,Nn] = A[M,K] @ Bt[Nn,K]^T ----------------
// BM=128, BN=128, BK=32. 8 warps in 4(m) x 2(n); warp tile 32x64 via m16n8k8.
// Nn % 128 == 0, K % 32 == 0. M guarded. cp.async double-buffered fp32 staging;
// hi/lo tf32 split at fragment load (3 MMAs per fragment pair -> ~fp32 accuracy).
#define GPAD 36
#define BUF_BYTES (2 * 128 * GPAD * 4)   // A-half + B-half per buffer
#define GSMEM_TOTAL (2 * BUF_BYTES)      // 73728 B

__global__ __launch_bounds__(256, 2)
void gemm_mma3(const float* __restrict__ A, const float* __restrict__ Bt,
               float* __restrict__ C, int M, int Nn, int K) {
    extern __shared__ float smem[];
    const uint32_t sb = smem_u32(smem);
    const int tid = threadIdx.x, lane = tid & 31, wid = tid >> 5;
    const int warpM = wid & 3, warpN = wid >> 2;
    const int row0 = blockIdx.y * 128, col0 = blockIdx.x * 128;
    const int gr = lane >> 2, gc = lane & 3;

    float c[2][8][4];
#pragma unroll
    for (int i = 0; i < 2; i++)
#pragma unroll
        for (int j = 0; j < 8; j++)
#pragma unroll
            for (int t = 0; t < 4; t++) c[i][j][t] = 0.f;

    const int nsc = K >> 5;
    const int r_st = tid >> 3, cq = tid & 7;   // staging coords (4 row-strides of 32)

    // stage chunk 0
    {
        uint32_t ab = sb, bb = sb + 128 * GPAD * 4;
#pragma unroll
        for (int t = 0; t < 4; t++) {
            int r = r_st + t * 32;
            cp16(ab + (uint32_t)(r * GPAD + cq * 4) * 4,
                 A + (size_t)(row0 + r) * K + cq * 4, (row0 + r < M) ? 16 : 0);
        }
#pragma unroll
        for (int t = 0; t < 4; t++) {
            int r = r_st + t * 32;
            cp16(bb + (uint32_t)(r * GPAD + cq * 4) * 4,
                 Bt + (size_t)(col0 + r) * K + cq * 4, 16);
        }
        CP_COMMIT();
    }

    for (int sc = 0; sc < nsc; sc++) {
        if (sc + 1 < nsc) {
            int k0 = (sc + 1) << 5;
            uint32_t base = sb + ((sc + 1) & 1) * BUF_BYTES;
            uint32_t ab = base, bb = base + 128 * GPAD * 4;
#pragma unroll
            for (int t = 0; t < 4; t++) {
                int r = r_st + t * 32;
                cp16(ab + (uint32_t)(r * GPAD + cq * 4) * 4,
                     A + (size_t)(row0 + r) * K + k0 + cq * 4,
                     (row0 + r < M) ? 16 : 0);
            }
#pragma unroll
            for (int t = 0; t < 4; t++) {
                int r = r_st + t * 32;
                cp16(bb + (uint32_t)(r * GPAD + cq * 4) * 4,
                     Bt + (size_t)(col0 + r) * K + k0 + cq * 4, 16);
            }
            CP_COMMIT();
            cp_wait<1>();
        } else {
            cp_wait<0>();
        }
        __syncthreads();

        const float* As = smem + (sc & 1) * (BUF_BYTES / 4);
        const float* Bs = As + 128 * GPAD;
#pragma unroll
        for (int ks = 0; ks < 4; ks++) {
            uint32_t ahi[2][4], alo[2][4];
#pragma unroll
            for (int i = 0; i < 2; i++) {
                const float* ap = As + (warpM * 32 + i * 16 + gr) * GPAD + ks * 8 + gc;
                float v0 = ap[0], v1 = ap[8 * GPAD], v2 = ap[4], v3 = ap[8 * GPAD + 4];
                ahi[i][0] = f2tf32(v0); alo[i][0] = f2tf32(v0 - __uint_as_float(ahi[i][0]));
                ahi[i][1] = f2tf32(v1); alo[i][1] = f2tf32(v1 - __uint_as_float(ahi[i][1]));
                ahi[i][2] = f2tf32(v2); alo[i][2] = f2tf32(v2 - __uint_as_float(ahi[i][2]));
                ahi[i][3] = f2tf32(v3); alo[i][3] = f2tf32(v3 - __uint_as_float(ahi[i][3]));
            }
#pragma unroll
            for (int j = 0; j < 8; j++) {
                const float* bp = Bs + (warpN * 64 + j * 8 + gr) * GPAD + ks * 8 + gc;
                float w0 = bp[0], w1 = bp[4];
                uint32_t bh0 = f2tf32(w0), bl0 = f2tf32(w0 - __uint_as_float(bh0));
                uint32_t bh1 = f2tf32(w1), bl1 = f2tf32(w1 - __uint_as_float(bh1));
#pragma unroll
                for (int i = 0; i < 2; i++) {
                    mma_tf32(c[i][j], alo[i][0], alo[i][1], alo[i][2], alo[i][3], bh0, bh1);
                    mma_tf32(c[i][j], ahi[i][0], ahi[i][1], ahi[i][2], ahi[i][3], bl0, bl1);
                    mma_tf32(c[i][j], ahi[i][0], ahi[i][1], ahi[i][2], ahi[i][3], bh0, bh1);
                }
            }
        }
        __syncthreads();
    }
    // epilogue
#pragma unroll
    for (int i = 0; i < 2; i++) {
        int r = row0 + warpM * 32 + i * 16 + gr;
#pragma unroll
        for (int j = 0; j < 8; j++) {
            int cc = col0 + warpN * 64 + j * 8 + 2 * gc;
            if (r < M)
                *(float2*)(C + (size_t)r * Nn + cc) = make_float2(c[i][j][0], c[i][j][1]);
            if (r + 8 < M)
                *(float2*)(C + (size_t)(r + 8) * Nn + cc) = make_float2(c[i][j][2], c[i][j][3]);
        }
    }
}

// ---------------- weight transpose: out[c][r] = in[r][c] ----------------
__global__ void k_transpose(const float* __restrict__ in, float* __restrict__ out,
                            int R, int C) {
    __shared__ float t[32][33];
    int bx = blockIdx.x * 32, by = blockIdx.y * 32;
    int x = bx + threadIdx.x;
#pragma unroll
    for (int j = 0; j < 32; j += 8) {
        int y = by + threadIdx.y + j;
        if (y < R && x < C) t[threadIdx.y + j][threadIdx.x] = in[(size_t)y * C + x];
    }
    __syncthreads();
    x = by + threadIdx.x;
#pragma unroll
    for (int j = 0; j < 32; j += 8) {
        int y = bx + threadIdx.y + j;
        if (y < C && x < R) out[(size_t)y * R + x] = t[threadIdx.x][threadIdx.y + j];
    }
}

// ---------------- CSR build ----------------
__global__ void k_zero_deg() {
    int i = blockIdx.x * blockDim.x + threadIdx.x;
    if (i < NN) g_deg[i] = 0;
}

__global__ void k_hist(const int* __restrict__ dst) {
    int e = blockIdx.x * blockDim.x + threadIdx.x;
    if (e < EE) atomicAdd(&g_deg[dst[e]], 1);
}

__global__ void k_scan() {
    const int PER = 20;
    __shared__ int wsum[32];
    int tid  = threadIdx.x;
    int base = tid * PER;
    int loc[PER];
    int s = 0;
#pragma unroll
    for (int i = 0; i < PER; i++) {
        int v = (base + i < NN) ? g_deg[base + i] : 0;
        loc[i] = s; s += v;
    }
    int lane = tid & 31, w = tid >> 5;
    int x = s;
#pragma unroll
    for (int o = 1; o < 32; o <<= 1) {
        int y = __shfl_up_sync(0xffffffffu, x, o);
        if (lane >= o) x += y;
    }
    if (lane == 31) wsum[w] = x;
    __syncthreads();
    if (w == 0) {
        int v = wsum[lane];
#pragma unroll
        for (int o = 1; o < 32; o <<= 1) {
            int y = __shfl_up_sync(0xffffffffu, v, o);
            if (lane >= o) v += y;
        }
        wsum[lane] = v;
    }
    __syncthreads();
    int pre = x - s + (w > 0 ? wsum[w - 1] : 0);
#pragma unroll
    for (int i = 0; i < PER; i++) {
        if (base + i < NN) {
            int o = pre + loc[i];
            g_off[base + i] = o;
            g_cur[base + i] = o;
        }
    }
}

__global__ void k_scatter(const int* __restrict__ dst) {
    int e = blockIdx.x * blockDim.x + threadIdx.x;
    if (e < EE) {
        int p = atomicAdd(&g_cur[dst[e]], 1);
        g_elist[p] = e;
    }
}

// ---------------- layer-1 edge kernels (proj layout: [N][1024], xl=0, xr=+512) ----------------
__global__ void k_score1(const int* __restrict__ src, const float* __restrict__ att1) {
    int gw   = (blockIdx.x * blockDim.x + threadIdx.x) >> 5;
    int lane = threadIdx.x & 31;
    if (gw >= NN) return;
    int d = g_deg[gw];
    if (d == 0) return;
    int start = g_off[gw];
    const float4* pv = (const float4*)g_p1;      // 256 float4 per row
    const float4* atv = (const float4*)att1;
    float4 xr[4], at[4];
#pragma unroll
    for (int j = 0; j < 4; j++) {
        xr[j] = pv[gw * 256 + 128 + lane * 4 + j];
        at[j] = atv[lane * 4 + j];
    }
    int e = g_elist[start];
    int s = src[e];
    for (int i = 0; i < d; i++) {
        int e2 = 0, s2 = 0;
        if (i + 1 < d) { e2 = g_elist[start + i + 1]; s2 = src[e2]; }
        float sum = 0.f;
#pragma unroll
        for (int j = 0; j < 4; j++) {
            float4 a = pv[s * 256 + lane * 4 + j];
            float t;
            t = a.x + xr[j].x; t = t > 0.f ? t : NEG * t; sum += t * at[j].x;
            t = a.y + xr[j].y; t = t > 0.f ? t : NEG * t; sum += t * at[j].y;
            t = a.z + xr[j].z; t = t > 0.f ? t : NEG * t; sum += t * at[j].z;
            t = a.w + xr[j].w; t = t > 0.f ? t : NEG * t; sum += t * at[j].w;
        }
        sum += __shfl_xor_sync(0xffffffffu, sum, 1);
        sum += __shfl_xor_sync(0xffffffffu, sum, 2);
        if ((lane & 3) == 0) g_alpha1[e * 8 + (lane >> 2)] = sum;
        e = e2; s = s2;
    }
}

__global__ void k_w1() {
    int gw   = (blockIdx.x * blockDim.x + threadIdx.x) >> 5;
    int lane = threadIdx.x & 31;
    if (gw >= NN) return;
    int d = g_deg[gw];
    if (d == 0) return;
    int start = g_off[gw];
    const float4* aL = (const float4*)g_alpha1;
    float4*       aS = (float4*)g_alpha1;
    float mx[8];
#pragma unroll
    for (int h = 0; h < 8; h++) mx[h] = -3.402823466e38f;
    for (int i = lane; i < d; i += 32) {
        int e = g_elist[start + i];
        float4 a = aL[e * 2], b = aL[e * 2 + 1];
        mx[0] = fmaxf(mx[0], a.x); mx[1] = fmaxf(mx[1], a.y);
        mx[2] = fmaxf(mx[2], a.z); mx[3] = fmaxf(mx[3], a.w);
        mx[4] = fmaxf(mx[4], b.x); mx[5] = fmaxf(mx[5], b.y);
        mx[6] = fmaxf(mx[6], b.z); mx[7] = fmaxf(mx[7], b.w);
    }
#pragma unroll
    for (int h = 0; h < 8; h++)
#pragma unroll
        for (int o = 16; o; o >>= 1)
            mx[h] = fmaxf(mx[h], __shfl_xor_sync(0xffffffffu, mx[h], o));
    float sm[8];
#pragma unroll
    for (int h = 0; h < 8; h++) sm[h] = 0.f;
    for (int i = lane; i < d; i += 32) {
        int e = g_elist[start + i];
        float4 a = aL[e * 2], b = aL[e * 2 + 1];
        a.x = expf(a.x - mx[0]); a.y = expf(a.y - mx[1]);
        a.z = expf(a.z - mx[2]); a.w = expf(a.w - mx[3]);
        b.x = expf(b.x - mx[4]); b.y = expf(b.y - mx[5]);
        b.z = expf(b.z - mx[6]); b.w = expf(b.w - mx[7]);
        sm[0] += a.x; sm[1] += a.y; sm[2] += a.z; sm[3] += a.w;
        sm[4] += b.x; sm[5] += b.y; sm[6] += b.z; sm[7] += b.w;
        aS[e * 2] = a; aS[e * 2 + 1] = b;
    }
#pragma unroll
    for (int h = 0; h < 8; h++)
#pragma unroll
        for (int o = 16; o; o >>= 1)
            sm[h] += __shfl_xor_sync(0xffffffffu, sm[h], o);
    if (lane == 0) {
#pragma unroll
        for (int h = 0; h < 8; h++) g_inv1[gw * 8 + h] = 1.f / (sm[h] + EPSI);
    }
}

__global__ void k_aggr1(const int* __restrict__ src, const float* __restrict__ b1) {
    int n   = blockIdx.x;
    int tid = threadIdx.x;           // 128: tid*4 channels, head = tid/16
    int d = g_deg[n], start = g_off[n];
    int h = tid >> 4;
    __shared__ float inv_s[8];
    if (tid < 8) inv_s[tid] = g_inv1[n * 8 + tid];
    __syncthreads();
    float inv = inv_s[h];
    const float4* pv = (const float4*)g_p1;      // xl = first 128 float4 of row
    float4 acc = make_float4(0.f, 0.f, 0.f, 0.f);
    int e = 0, s = 0;
    if (d > 0) { e = g_elist[start]; s = src[e]; }
    for (int i = 0; i < d; i++) {
        int e2 = 0, s2 = 0;
        if (i + 1 < d) { e2 = g_elist[start + i + 1]; s2 = src[e2]; }
        float w  = g_alpha1[e * 8 + h] * inv;
        float4 v = pv[s * 256 + tid];
        acc.x += w * v.x; acc.y += w * v.y; acc.z += w * v.z; acc.w += w * v.w;
        e = e2; s = s2;
    }
    int c0 = tid * 4;
    float4 bb = *(const float4*)(b1 + c0);
    float4 o;
    o.x = acc.x + bb.x; o.x = o.x > 0.f ? o.x : expm1f(o.x);
    o.y = acc.y + bb.y; o.y = o.y > 0.f ? o.y : expm1f(o.y);
    o.z = acc.z + bb.z; o.z = o.z > 0.f ? o.z : expm1f(o.z);
    o.w = acc.w + bb.w; o.w = o.w > 0.f ? o.w : expm1f(o.w);
    ((float4*)g_h)[n * 128 + tid] = o;
}

// ---------------- layer-2 edge kernels (proj layout: [N][128], xl=0, xr=+64) ----------------
__global__ void k_score2(const int* __restrict__ src, const float* __restrict__ att2) {
    int gw   = (blockIdx.x * blockDim.x + threadIdx.x) >> 5;
    int lane = threadIdx.x & 31;
    if (gw >= NN) return;
    int d = g_deg[gw];
    if (d == 0) return;
    int start = g_off[gw];
    const float2* pv = (const float2*)g_p2;      // 64 float2 per row
    float2 xr = pv[gw * 64 + 32 + lane];
    float2 at = ((const float2*)att2)[lane];
    int e = g_elist[start];
    int s = src[e];
    for (int i = 0; i < d; i++) {
        int e2 = 0, s2 = 0;
        if (i + 1 < d) { e2 = g_elist[start + i + 1]; s2 = src[e2]; }
        float2 a = pv[s * 64 + lane];
        float t0 = a.x + xr.x; t0 = t0 > 0.f ? t0 : NEG * t0;
        float t1 = a.y + xr.y; t1 = t1 > 0.f ? t1 : NEG * t1;
        float sum = t0 * at.x + t1 * at.y;
#pragma unroll
        for (int o = 16; o; o >>= 1) sum += __shfl_xor_sync(0xffffffffu, sum, o);
        if (lane == 0) g_alpha2[e] = sum;
        e = e2; s = s2;
    }
}

__global__ void k_w2() {
    int gw   = (blockIdx.x * blockDim.x + threadIdx.x) >> 5;
    int lane = threadIdx.x & 31;
    if (gw >= NN) return;
    int d = g_deg[gw];
    if (d == 0) return;
    int start = g_off[gw];
    float mx = -3.402823466e38f;
    for (int i = lane; i < d; i += 32) mx = fmaxf(mx, g_alpha2[g_elist[start + i]]);
#pragma unroll
    for (int o = 16; o; o >>= 1) mx = fmaxf(mx, __shfl_xor_sync(0xffffffffu, mx, o));
    float sm = 0.f;
    for (int i = lane; i < d; i += 32) {
        int e = g_elist[start + i];
        float ex = expf(g_alpha2[e] - mx);
        g_alpha2[e] = ex;
        sm += ex;
    }
#pragma unroll
    for (int o = 16; o; o >>= 1) sm += __shfl_xor_sync(0xffffffffu, sm, o);
    if (lane == 0) g_inv2[gw] = 1.f / (sm + EPSI);
}

__global__ void k_aggr2(const int* __restrict__ src, const float* __restrict__ b2,
                        float* __restrict__ out) {
    int n   = blockIdx.x;
    int tid = threadIdx.x;            // 64, one channel each
    int d = g_deg[n], start = g_off[n];
    float inv = g_inv2[n];
    float acc = 0.f;
    int e = 0, s = 0;
    if (d > 0) { e = g_elist[start]; s = src[e]; }
    for (int i = 0; i < d; i++) {
        int e2 = 0, s2 = 0;
        if (i + 1 < d) { e2 = g_elist[start + i + 1]; s2 = src[e2]; }
        float w = g_alpha2[e] * inv;
        acc += w * g_p2[s * 128 + tid];
        e = e2; s = s2;
    }
    out[n * 64 + tid] = acc + b2[tid];
}

// ---------------- launch ----------------
extern "C" void kernel_launch(void* const* d_in, const int* in_sizes, int n_in,
                              void* d_out, int out_size) {
    const float* x    = (const float*)d_in[0];
    const int*   ei   = (const int*)d_in[1];
    const float* Wl1  = (const float*)d_in[2];
    const float* Wr1  = (const float*)d_in[3];
    const float* att1 = (const float*)d_in[4];
    const float* b1   = (const float*)d_in[5];
    const float* Wl2  = (const float*)d_in[6];
    const float* Wr2  = (const float*)d_in[7];
    const float* att2 = (const float*)d_in[8];
    const float* b2   = (const float*)d_in[9];
    float* out = (float*)d_out;
    const int* srcA = ei;
    const int* dstA = ei + EE;

    float *p1, *hb, *p2, *wtc1, *wtc2;
    cudaGetSymbolAddress((void**)&p1, g_p1);
    cudaGetSymbolAddress((void**)&hb, g_h);
    cudaGetSymbolAddress((void**)&p2, g_p2);
    cudaGetSymbolAddress((void**)&wtc1, g_wtc1);
    cudaGetSymbolAddress((void**)&wtc2, g_wtc2);

    cudaFuncSetAttribute(gemm_mma3, cudaFuncAttributeMaxDynamicSharedMemorySize,
                         GSMEM_TOTAL);

    dim3 tb(32, 8);
    // 0,1: layer-1 weight transposes into concatenated buffer
    k_transpose<<<dim3(H1 / 32, FIN / 32), tb>>>(Wl1, wtc1, FIN, H1);
    k_transpose<<<dim3(H1 / 32, FIN / 32), tb>>>(Wr1, wtc1 + H1 * FIN, FIN, H1);
    // 2-4: CSR histogram + scan
    k_zero_deg<<<(NN + 255) / 256, 256>>>();
    k_hist<<<(EE + 255) / 256, 256>>>(dstA);
    k_scan<<<1, 1024>>>();
    // 5: fused layer-1 projection GEMM (profiled launch)
    gemm_mma3<<<dim3(1024 / 128, (NN + 127) / 128), 256, GSMEM_TOTAL>>>(
        x, wtc1, p1, NN, 1024, FIN);
    // 6: CSR scatter
    k_scatter<<<(EE + 255) / 256, 256>>>(dstA);
    // 7-9: layer-1 attention + aggregate
    k_score1<<<(NN * 32 + 255) / 256, 256>>>(srcA, att1);
    k_w1<<<(NN * 32 + 255) / 256, 256>>>();
    k_aggr1<<<NN, 128>>>(srcA, b1);
    // 10,11: layer-2 weight transposes
    k_transpose<<<dim3(NCLS / 32, H1 / 32), tb>>>(Wl2, wtc2, H1, NCLS);
    k_transpose<<<dim3(NCLS / 32, H1 / 32), tb>>>(Wr2, wtc2 + NCLS * H1, H1, NCLS);
    // 12: fused layer-2 projection GEMM
    gemm_mma3<<<dim3(1, (NN + 127) / 128), 256, GSMEM_TOTAL>>>(
        hb, wtc2, p2, NN, 128, H1);
    // 13-15: layer-2 attention + aggregate
    k_score2<<<(NN * 32 + 255) / 256, 256>>>(srcA, att2);
    k_w2<<<(NN * 32 + 255) / 256, 256>>>();
    k_aggr2<<<NN, 64>>>(srcA, b2, out);
}